// round 4
// baseline (speedup 1.0000x reference)
#include <cuda_runtime.h>
#include <cuda_bf16.h>
#include <cstdint>

// HyperedgeMaxAggregator: out[s, f] = max over members i with segment_ids[i]==s
// of features[node_ids[i], f].  segment_ids sorted. F = 64.
//
// R4: float4 + half-warp row ownership. 16 lanes x float4 = one 256B row, so a
// warp processes TWO members per iteration (each half-warp owns an independent
// 64-member chunk). Halves warp-instructions/member vs R3 (issue was 51%,
// ~90% of measured LTS cap). Tails handled by index clamping (idempotent for
// max). Interior segments: plain st.128; chunk-boundary segments: float atomics
// onto -inf-initialized output.

#define FEAT 64
#define HCHUNK 64          // members per HALF-warp (warp covers 128)
#define WPB 8              // warps per block (256 threads)
#define PF 4               // prefetch group (pairs of rows in flight)

__device__ int g_ids_are_64 = 0;

static __device__ __forceinline__ float neg_inf_f() {
    return __int_as_float(0xff800000);
}

static __device__ __forceinline__ void atomic_max_float(float* addr, float v) {
    if (v >= 0.0f) {
        atomicMax((int*)addr, __float_as_int(v));
    } else {
        atomicMin((unsigned int*)addr, __float_as_uint(v));
    }
}

__global__ void init_kernel(float* __restrict__ out, int out_size,
                            const int* __restrict__ node_ids_as_i32) {
    int tid = blockIdx.x * blockDim.x + threadIdx.x;
    if (tid == 0) {
        // int64 ids (values < 2^31, little-endian) have all odd 32-bit words 0.
        bool all_zero = true;
#pragma unroll
        for (int k = 1; k <= 15; k += 2) {
            all_zero = all_zero && (node_ids_as_i32[k] == 0);
        }
        g_ids_are_64 = all_zero ? 1 : 0;
    }
    const float ni = neg_inf_f();
    float4 v4 = make_float4(ni, ni, ni, ni);
    int n4 = out_size >> 2;
    float4* out4 = (float4*)out;
    for (int i = tid; i < n4; i += gridDim.x * blockDim.x) {
        out4[i] = v4;
    }
}

template <bool IS64>
static __device__ __forceinline__ int get_id(const void* __restrict__ p, int i) {
    if (IS64) {
        return (int)__ldg(&((const long long*)p)[i]);
    } else {
        return __ldg(&((const int*)p)[i]);
    }
}

// 16 lanes (hl = lane&15) own the full 64-float row as float4 each.
static __device__ __forceinline__ void flush_seg(float* __restrict__ out,
                                                 int sid, int hl,
                                                 float4 m, bool use_atomic) {
    float* p = out + (((uint32_t)sid << 6) + (uint32_t)(hl << 2));
    if (use_atomic) {
        atomic_max_float(p,     m.x);
        atomic_max_float(p + 1, m.y);
        atomic_max_float(p + 2, m.z);
        atomic_max_float(p + 3, m.w);
    } else {
        *(float4*)p = m;
    }
}

template <bool IS64>
static __device__ __forceinline__ void seg_body(
    const char* __restrict__ feat_bytes,
    const void* __restrict__ node_ids,
    const void* __restrict__ seg_ids,
    float* __restrict__ out,
    int n_members)
{
    int gwarp = (blockIdx.x * blockDim.x + threadIdx.x) >> 5;
    int lane  = threadIdx.x & 31;
    int half  = lane >> 4;            // 0 or 1: which member stream
    int hl    = lane & 15;            // position within half-warp
    int hbase16 = half << 4;

    int hstart = gwarp * (2 * HCHUNK) + half * HCHUNK;
    int nlast  = n_members - 1;
    if (gwarp * (2 * HCHUNK) > nlast) return;   // whole warp past the end

    // this lane's 16B slice within any feature row
    const char* fbase = feat_bytes + (uint32_t)(hl << 4);

    const float ni = neg_inf_f();
    float4 m = make_float4(ni, ni, ni, ni);
    int  cur = get_id<IS64>(seg_ids, min(hstart, nlast));
    bool first_seg = true;            // may extend into previous chunk

    for (int b = 0; b < HCHUNK; b += 16) {
        // coalesced id loads: lanes 0-15 -> stream A, 16-31 -> stream B
        int myi    = min(hstart + b + hl, nlast);      // clamp = idempotent dup
        int my_nid = get_id<IS64>(node_ids, myi);
        int my_sid = get_id<IS64>(seg_ids,  myi);

        // per-half transition bitmap (hl==0 compares against running cur)
        int up   = __shfl_up_sync(0xffffffffu, my_sid, 1);
        bool dif = (hl == 0) ? (my_sid != cur) : (my_sid != up);
        uint32_t tmask = __ballot_sync(0xffffffffu, dif);

#pragma unroll
        for (int j0 = 0; j0 < 16; j0 += PF) {
            float4 v[PF];
            // PF independent 256B-row loads in flight (2 members / LDG.128)
#pragma unroll
            for (int k = 0; k < PF; ++k) {
                int nid = __shfl_sync(0xffffffffu, my_nid, j0 + k + hbase16);
                v[k] = __ldg((const float4*)(fbase + ((uint32_t)nid << 8)));
            }
#pragma unroll
            for (int k = 0; k < PF; ++k) {
                const int j = j0 + k;
                if ((tmask >> j) & 0x00010001u) {     // either half transitions
                    int  s_j  = __shfl_sync(0xffffffffu, my_sid, j + hbase16);
                    bool mine = (tmask >> (j + hbase16)) & 1u;
                    if (mine) {                        // half-warp divergent
                        flush_seg(out, cur, hl, m, first_seg);
                        first_seg = false;
                        cur = s_j;
                        m = make_float4(ni, ni, ni, ni);
                    }
                }
                m.x = fmaxf(m.x, v[k].x);
                m.y = fmaxf(m.y, v[k].y);
                m.z = fmaxf(m.z, v[k].z);
                m.w = fmaxf(m.w, v[k].w);
            }
        }
    }
    // last segment may extend into the next chunk -> atomic
    flush_seg(out, cur, hl, m, true);
}

__global__ void __launch_bounds__(WPB * 32, 5)
seg_max_kernel(const float* __restrict__ features,
               const void* __restrict__ node_ids,
               const void* __restrict__ seg_ids,
               float* __restrict__ out,
               int n_members)
{
    const char* fb = (const char*)features;
    if (g_ids_are_64) {
        seg_body<true>(fb, node_ids, seg_ids, out, n_members);
    } else {
        seg_body<false>(fb, node_ids, seg_ids, out, n_members);
    }
}

extern "C" void kernel_launch(void* const* d_in, const int* in_sizes, int n_in,
                              void* d_out, int out_size) {
    const float* features = (const float*)d_in[0];
    const void*  node_ids = d_in[1];
    const void*  seg_ids  = d_in[2];
    float*       out      = (float*)d_out;

    int n_members = in_sizes[1];

    {
        int n4 = out_size >> 2;
        int threads = 256;
        int blocks = (n4 + threads - 1) / threads;
        if (blocks > 1024) blocks = 1024;
        if (blocks < 1) blocks = 1;
        init_kernel<<<blocks, threads>>>(out, out_size, (const int*)node_ids);
    }

    if (n_members > 0) {
        int warps  = (n_members + 2 * HCHUNK - 1) / (2 * HCHUNK);
        int blocks = (warps + WPB - 1) / WPB;
        seg_max_kernel<<<blocks, WPB * 32>>>(features, node_ids, seg_ids, out,
                                             n_members);
    }
}

// round 6
// speedup vs baseline: 1.1397x; 1.1397x over previous
#include <cuda_runtime.h>
#include <cuda_bf16.h>
#include <cstdint>

// HyperedgeMaxAggregator: out[s, f] = max over members i with segment_ids[i]==s
// of features[node_ids[i], f].  segment_ids sorted. F = 64.
//
// R6 == R5 resubmit (R5 bench died to container infra, not the kernel):
// R3 structure (float2, 32 lanes/row, ballot transition mask, 32-bit addr)
// + software-pipelined id loads across batches + finer blocks (128 thr).

#define FEAT 64
#define CHUNK 64           // members per warp
#define WPB 4              // warps per block (128 threads)
#define PF 8               // prefetch group (MLP)

__device__ int g_ids_are_64 = 0;

static __device__ __forceinline__ float neg_inf_f() {
    return __int_as_float(0xff800000);
}

static __device__ __forceinline__ void atomic_max_float(float* addr, float v) {
    if (v >= 0.0f) {
        atomicMax((int*)addr, __float_as_int(v));
    } else {
        atomicMin((unsigned int*)addr, __float_as_uint(v));
    }
}

__global__ void init_kernel(float* __restrict__ out, int out_size,
                            const int* __restrict__ node_ids_as_i32) {
    int tid = blockIdx.x * blockDim.x + threadIdx.x;
    if (tid == 0) {
        // int64 ids (values < 2^31, little-endian) have all odd 32-bit words 0.
        bool all_zero = true;
#pragma unroll
        for (int k = 1; k <= 15; k += 2) {
            all_zero = all_zero && (node_ids_as_i32[k] == 0);
        }
        g_ids_are_64 = all_zero ? 1 : 0;
    }
    const float ni = neg_inf_f();
    float4 v4 = make_float4(ni, ni, ni, ni);
    int n4 = out_size >> 2;
    float4* out4 = (float4*)out;
    for (int i = tid; i < n4; i += gridDim.x * blockDim.x) {
        out4[i] = v4;
    }
}

template <bool IS64>
static __device__ __forceinline__ int get_id(const void* __restrict__ p, int i) {
    if (IS64) {
        return (int)__ldg(&((const long long*)p)[i]);
    } else {
        return __ldg(&((const int*)p)[i]);
    }
}

static __device__ __forceinline__ void flush_seg(float* __restrict__ out,
                                                 int sid, int lane,
                                                 float2 m, bool use_atomic) {
    // 32-bit offset: sid*64 + lane*2 floats (out <= 12.8 MB)
    float* p = out + (((uint32_t)sid << 6) + (uint32_t)(lane << 1));
    if (use_atomic) {
        atomic_max_float(p,     m.x);
        atomic_max_float(p + 1, m.y);
    } else {
        *(float2*)p = m;
    }
}

template <bool IS64>
static __device__ __forceinline__ void seg_body(
    const char* __restrict__ feat_bytes,
    const void* __restrict__ node_ids,
    const void* __restrict__ seg_ids,
    float* __restrict__ out,
    int n_members)
{
    int gwarp = (blockIdx.x * blockDim.x + threadIdx.x) >> 5;
    int lane  = threadIdx.x & 31;
    int start = gwarp * CHUNK;
    if (start >= n_members) return;
    int end = min(start + CHUNK, n_members);

    // per-lane adjusted base: row byte offset is nid << 8 (features <= 25.6 MB)
    const char* fbase = feat_bytes + (uint32_t)(lane << 3);

    const float ni = neg_inf_f();
    int    cur = get_id<IS64>(seg_ids, start);
    float2 m   = make_float2(ni, ni);
    bool first_seg = true;   // first segment may extend into previous chunk

    int base = start;
    int my_nid = 0, my_sid = 0;
    bool have = (base + 32 <= end);
    if (have) {
        my_nid = get_id<IS64>(node_ids, base + lane);
        my_sid = get_id<IS64>(seg_ids,  base + lane);
    }

    // ---- fast path: full 32-member batches, id loads pipelined ----
    while (have) {
        bool more = (base + 64 <= end);
        int nxt_nid = 0, nxt_sid = 0;
        if (more) {
            // issue next batch's id loads before consuming this batch
            nxt_nid = get_id<IS64>(node_ids, base + 32 + lane);
            nxt_sid = get_id<IS64>(seg_ids,  base + 32 + lane);
        }

        // transition bitmap: bit k set iff member base+k starts a new segment
        int up   = __shfl_up_sync(0xffffffffu, my_sid, 1);
        bool dif = (lane == 0) ? (my_sid != cur) : (my_sid != up);
        uint32_t tmask = __ballot_sync(0xffffffffu, dif);

#pragma unroll
        for (int j = 0; j < 32; j += PF) {
            float2 v[PF];
            // PF independent feature loads in flight
#pragma unroll
            for (int k = 0; k < PF; ++k) {
                int nid = __shfl_sync(0xffffffffu, my_nid, j + k);
                v[k] = __ldg((const float2*)(fbase + ((uint32_t)nid << 8)));
            }
#pragma unroll
            for (int k = 0; k < PF; ++k) {
                if (tmask & (1u << (j + k))) {      // warp-uniform branch
                    flush_seg(out, cur, lane, m, first_seg);
                    first_seg = false;
                    cur = __shfl_sync(0xffffffffu, my_sid, j + k);
                    m = make_float2(ni, ni);
                }
                m.x = fmaxf(m.x, v[k].x);
                m.y = fmaxf(m.y, v[k].y);
            }
        }

        base += 32;
        my_nid = nxt_nid;
        my_sid = nxt_sid;
        have = more;
    }
    // ---- tail: serial ----
    for (int i = base; i < end; ++i) {
        int s = get_id<IS64>(seg_ids, i);
        if (s != cur) {
            flush_seg(out, cur, lane, m, first_seg);
            first_seg = false;
            cur = s;
            m = make_float2(ni, ni);
        }
        int nid = get_id<IS64>(node_ids, i);
        float2 v = __ldg((const float2*)(fbase + ((uint32_t)nid << 8)));
        m.x = fmaxf(m.x, v.x);
        m.y = fmaxf(m.y, v.y);
    }
    // last segment may extend into the next chunk -> atomic
    flush_seg(out, cur, lane, m, true);
}

__global__ void __launch_bounds__(WPB * 32, 12)
seg_max_kernel(const float* __restrict__ features,
               const void* __restrict__ node_ids,
               const void* __restrict__ seg_ids,
               float* __restrict__ out,
               int n_members)
{
    const char* fb = (const char*)features;
    if (g_ids_are_64) {
        seg_body<true>(fb, node_ids, seg_ids, out, n_members);
    } else {
        seg_body<false>(fb, node_ids, seg_ids, out, n_members);
    }
}

extern "C" void kernel_launch(void* const* d_in, const int* in_sizes, int n_in,
                              void* d_out, int out_size) {
    const float* features = (const float*)d_in[0];
    const void*  node_ids = d_in[1];
    const void*  seg_ids  = d_in[2];
    float*       out      = (float*)d_out;

    int n_members = (n_in > 1) ? in_sizes[1] : 0;

    {
        int n4 = out_size >> 2;
        int threads = 256;
        int blocks = (n4 + threads - 1) / threads;
        if (blocks > 1024) blocks = 1024;
        if (blocks < 1) blocks = 1;
        init_kernel<<<blocks, threads>>>(out, out_size, (const int*)node_ids);
    }

    if (n_members > 0) {
        int warps  = (n_members + CHUNK - 1) / CHUNK;
        int blocks = (warps + WPB - 1) / WPB;
        seg_max_kernel<<<blocks, WPB * 32>>>(features, node_ids, seg_ids, out,
                                             n_members);
    }
}